// round 14
// baseline (speedup 1.0000x reference)
#include <cuda_runtime.h>
#include <cuda_bf16.h>
#include <cstdint>

#define AD 512
#define BB 16
#define HH 8
#define CROSS_C 359   // A - int(A*0.3) = 512 - 153

// ---------------- scratch (static device globals; no allocs) ----------------
__device__ __nv_bfloat16 g_Qhi[BB * AD * AD], g_Qlo[BB * AD * AD];
__device__ __nv_bfloat16 g_Khi[BB * AD * AD], g_Klo[BB * AD * AD];
__device__ __nv_bfloat16 g_Wqhi[AD * AD], g_Wqlo[AD * AD];
__device__ __nv_bfloat16 g_Wkhi[AD * AD], g_Wklo[AD * AD];
__device__ __nv_bfloat16 g_QpThi[BB * AD * AD], g_QpTlo[BB * AD * AD];
__device__ __nv_bfloat16 g_KpThi[BB * AD * AD], g_KpTlo[BB * AD * AD];
__device__ float g_am0[BB * AD * AD];
__device__ float g_Vp[BB * AD];
__device__ float g_att[BB * HH * AD];
__device__ unsigned g_bits[BB * HH * AD * AD];   // 134 MB of threefry output

// ---------------- threefry2x32 (20 rounds, JAX-compatible) ----------------
__device__ __forceinline__ void tf2x32(unsigned k0, unsigned k1,
                                       unsigned x0, unsigned x1,
                                       unsigned &o0, unsigned &o1) {
    unsigned k2 = k0 ^ k1 ^ 0x1BD11BDAu;
    x0 += k0; x1 += k1;
#define TFR(r) { x0 += x1; x1 = __funnelshift_l(x1, x1, r); x1 ^= x0; }
    TFR(13) TFR(15) TFR(26) TFR(6)   x0 += k1; x1 += k2 + 1u;
    TFR(17) TFR(29) TFR(16) TFR(24)  x0 += k2; x1 += k0 + 2u;
    TFR(13) TFR(15) TFR(26) TFR(6)   x0 += k0; x1 += k1 + 3u;
    TFR(17) TFR(29) TFR(16) TFR(24)  x0 += k1; x1 += k2 + 4u;
    TFR(13) TFR(15) TFR(26) TFR(6)   x0 += k2; x1 += k0 + 5u;
#undef TFR
    o0 = x0; o1 = x1;
}

__device__ __forceinline__ float bits_to_unit(unsigned bits) {
    return __uint_as_float((bits >> 9) | 0x3f800000u) - 1.0f;
}

// ---------------- bf16 split helpers ----------------
__device__ __forceinline__ void split_bf16(float x, __nv_bfloat16 &hi, __nv_bfloat16 &lo) {
    hi = __float2bfloat16_rn(x);
    lo = __float2bfloat16_rn(x - __bfloat162float(hi));
}

__device__ __forceinline__ void mma_bf16(float* c, const unsigned* a, const unsigned* b) {
    asm volatile(
        "mma.sync.aligned.m16n8k16.row.col.f32.bf16.bf16.f32 "
        "{%0,%1,%2,%3}, {%4,%5,%6,%7}, {%8,%9}, {%0,%1,%2,%3};"
        : "+f"(c[0]), "+f"(c[1]), "+f"(c[2]), "+f"(c[3])
        : "r"(a[0]), "r"(a[1]), "r"(a[2]), "r"(a[3]), "r"(b[0]), "r"(b[1]));
}

__device__ __forceinline__ void ldsm_x4(unsigned* r, unsigned addr) {
    asm volatile("ldmatrix.sync.aligned.m8n8.x4.shared.b16 {%0,%1,%2,%3}, [%4];"
                 : "=r"(r[0]), "=r"(r[1]), "=r"(r[2]), "=r"(r[3]) : "r"(addr));
}
__device__ __forceinline__ void ldsm_x2(unsigned* r, unsigned addr) {
    asm volatile("ldmatrix.sync.aligned.m8n8.x2.shared.b16 {%0,%1}, [%2];"
                 : "=r"(r[0]), "=r"(r[1]) : "r"(addr));
}

#define CP16(dst_s, src_g) \
    asm volatile("cp.async.cg.shared.global [%0], [%1], 16;\n" :: "r"(dst_s), "l"(src_g))
#define CP_COMMIT asm volatile("cp.async.commit_group;\n" ::)
#define CP_WAIT(n) asm volatile("cp.async.wait_group %0;\n" :: "n"(n))

__device__ __forceinline__ unsigned saddr(const void* p) {
    return (unsigned)__cvta_generic_to_shared(p);
}

// ---------------- prepass: split fp32 inputs into bf16 hi/lo ----------------
__global__ __launch_bounds__(256) void split_pre(const float* __restrict__ Q,
                                                 const float* __restrict__ K,
                                                 const float* __restrict__ WQw,
                                                 const float* __restrict__ WKw) {
    const int N1 = BB * AD * AD;
    const int N2 = AD * AD;
    const int total4 = (2 * N1 + 2 * N2) / 4;
    for (int v = blockIdx.x * blockDim.x + threadIdx.x; v < total4;
         v += gridDim.x * blockDim.x) {
        int i = v * 4;
        const float* src; __nv_bfloat16 *dh, *dl; int off;
        if (i < N1)              { src = Q;   dh = g_Qhi;  dl = g_Qlo;  off = i; }
        else if (i < 2 * N1)     { src = K;   dh = g_Khi;  dl = g_Klo;  off = i - N1; }
        else if (i < 2 * N1 + N2){ src = WQw; dh = g_Wqhi; dl = g_Wqlo; off = i - 2 * N1; }
        else                     { src = WKw; dh = g_Wkhi; dl = g_Wklo; off = i - 2 * N1 - N2; }
        float4 x = *(const float4*)(src + off);
        __nv_bfloat16 h[4], l[4];
        split_bf16(x.x, h[0], l[0]);
        split_bf16(x.y, h[1], l[1]);
        split_bf16(x.z, h[2], l[2]);
        split_bf16(x.w, h[3], l[3]);
        *(uint2*)(dh + off) = *(uint2*)h;
        *(uint2*)(dl + off) = *(uint2*)l;
    }
}

// ---------------- mut_pre: threefry random bits -----------------------------
// 128-thr blocks, reg-capped so one block co-resides with the 2 GEMM CTAs
// (which are capped at 116 regs). 2 independent chains per trip for ILP.
__global__ void __maxnreg__(40)
mut_pre(unsigned km0, unsigned km1) {
    const int N = BB * HH * AD * AD;
    int stride = gridDim.x * blockDim.x;      // 4096*128 = 524288; N % (2*stride) == 0
    for (int f = blockIdx.x * blockDim.x + threadIdx.x; f < N; f += 2 * stride) {
        unsigned a0, a1, b0, b1;
        tf2x32(km0, km1, 0u, (unsigned)f, a0, a1);
        tf2x32(km0, km1, 0u, (unsigned)(f + stride), b0, b1);
        g_bits[f] = a0 ^ a1;
        g_bits[f + stride] = b0 ^ b1;
    }
}

// ---------------- 3xBF16 TN GEMM with ldmatrix ------------------------------
// CTA 128x128, 8 warps (2x4), warp tile 64x32, BK=16, m16n8k16 bf16 mma.
// Smem rows padded to 48B so ldmatrix row-addresses are bank-conflict-free.
// 4 stages (96 KB) -> 2 CTAs/SM = 16 warps/SM (pinned by smem: 2x96=192<=228KB).
// Regs capped at 116 (116*512=59392 <= 64K) leaving 6144 spare so a 128-thr
// mut_pre block (<=40 regs = 5120) can co-reside per SM.
#define NSTAGE 4
#define ROWB 48
#define ARR_B (128 * ROWB)               // 6144 B per array
#define STAGE_B (4 * ARR_B)              // 24576 B per stage
#define GEMM_SMEM_BYTES (NSTAGE * STAGE_B)   // 96 KB

template<bool SPLIT_OUT>
__device__ __forceinline__ void gemm_bf16_core(
    const __nv_bfloat16* __restrict__ Ahi, const __nv_bfloat16* __restrict__ Alo,
    const __nv_bfloat16* __restrict__ Bhi, const __nv_bfloat16* __restrict__ Blo,
    float* __restrict__ Cf, __nv_bfloat16* __restrict__ Chi,
    __nv_bfloat16* __restrict__ Clo,
    const float* __restrict__ bias, float scale) {
    extern __shared__ char smb[];
    const unsigned smem_u = saddr(smb);
    int tid = threadIdx.x;
    int lane = tid & 31, wid = tid >> 5;
    int wm = wid & 1, wn = wid >> 1;       // 2 x 4 warp grid
    int m0 = blockIdx.y * 128, n0 = blockIdx.x * 128;
    int qr = lane >> 2, qc = lane & 3;

    float acc[4][4][4];
#pragma unroll
    for (int mi = 0; mi < 4; mi++)
#pragma unroll
        for (int ni = 0; ni < 4; ni++)
#pragma unroll
            for (int e = 0; e < 4; e++) acc[mi][ni][e] = 0.f;

    int lr = tid >> 1;            // row 0..127
    int lc = (tid & 1) * 8;       // element 0 or 8

#define ISSUE(ch, st)                                                          \
    {                                                                          \
        int k0_ = (ch) * 16 + lc;                                              \
        unsigned d_ = smem_u + (st) * STAGE_B + lr * ROWB + lc * 2;            \
        CP16(d_,              Ahi + (size_t)(m0 + lr) * AD + k0_);             \
        CP16(d_ + ARR_B,      Alo + (size_t)(m0 + lr) * AD + k0_);             \
        CP16(d_ + 2 * ARR_B,  Bhi + (size_t)(n0 + lr) * AD + k0_);             \
        CP16(d_ + 3 * ARR_B,  Blo + (size_t)(n0 + lr) * AD + k0_);             \
        CP_COMMIT;                                                             \
    }

    ISSUE(0, 0)
    ISSUE(1, 1)
    ISSUE(2, 2)

    // per-lane ldmatrix address offsets (within an array)
    unsigned a_off = (unsigned)((wm * 64 + (lane & 15)) * ROWB + ((lane >> 4) << 4));
    unsigned b_off = (unsigned)((wn * 32 + (lane & 7)) * ROWB + (((lane >> 3) & 1) << 4));

    const int NIT = AD / 16;   // 32
    for (int it = 0; it < NIT; ++it) {
        int s = it & (NSTAGE - 1);
        int rem = NIT - 1 - it;
        if (rem >= 2) CP_WAIT(2); else if (rem == 1) CP_WAIT(1); else CP_WAIT(0);
        __syncthreads();
        if (it + 3 < NIT) ISSUE(it + 3, (it + 3) & (NSTAGE - 1))

        unsigned base = smem_u + s * STAGE_B;
        unsigned ah[4][4], al[4][4];
#pragma unroll
        for (int mi = 0; mi < 4; mi++) {
            unsigned addr = base + a_off + mi * (16 * ROWB);
            ldsm_x4(ah[mi], addr);
            ldsm_x4(al[mi], addr + ARR_B);
        }
#pragma unroll
        for (int ni = 0; ni < 4; ni++) {
            unsigned addrB = base + 2 * ARR_B + b_off + ni * (8 * ROWB);
            unsigned bh[2], bl[2];
            ldsm_x2(bh, addrB);
            ldsm_x2(bl, addrB + ARR_B);
#pragma unroll
            for (int mi = 0; mi < 4; mi++) {
                mma_bf16(acc[mi][ni], ah[mi], bh);
                mma_bf16(acc[mi][ni], ah[mi], bl);
                mma_bf16(acc[mi][ni], al[mi], bh);
            }
        }
    }
#undef ISSUE

    // epilogue
#pragma unroll
    for (int mi = 0; mi < 4; mi++) {
        int r0 = m0 + wm * 64 + mi * 16 + qr;
        float b0 = 0.f, b1 = 0.f;
        if (bias) { b0 = __ldg(bias + r0); b1 = __ldg(bias + r0 + 8); }
#pragma unroll
        for (int ni = 0; ni < 4; ni++) {
            int c0 = n0 + wn * 32 + ni * 8 + qc * 2;
            float v00 = acc[mi][ni][0] * scale + b0;
            float v01 = acc[mi][ni][1] * scale + b0;
            float v10 = acc[mi][ni][2] * scale + b1;
            float v11 = acc[mi][ni][3] * scale + b1;
            if (SPLIT_OUT) {
                __nv_bfloat16 h[2], l[2];
                split_bf16(v00, h[0], l[0]);
                split_bf16(v01, h[1], l[1]);
                *(unsigned*)&Chi[(size_t)r0 * AD + c0] = *(unsigned*)h;
                *(unsigned*)&Clo[(size_t)r0 * AD + c0] = *(unsigned*)l;
                split_bf16(v10, h[0], l[0]);
                split_bf16(v11, h[1], l[1]);
                *(unsigned*)&Chi[(size_t)(r0 + 8) * AD + c0] = *(unsigned*)h;
                *(unsigned*)&Clo[(size_t)(r0 + 8) * AD + c0] = *(unsigned*)l;
            } else {
                float2 v0 = {v00, v01}, v1 = {v10, v11};
                *(float2*)&Cf[(size_t)r0 * AD + c0] = v0;
                *(float2*)&Cf[(size_t)(r0 + 8) * AD + c0] = v1;
            }
        }
    }
}

// merged Q/K projection: QpT[i][j] = sum_t W[i,t]*X[j,t] + bias[i] (split out)
__global__ void __maxnreg__(116) proj_kernel(
    const float* __restrict__ WQb, const float* __restrict__ WKb) {
    int z = blockIdx.z;
    int b = z & (BB - 1);
    int sel = z >> 4;
    size_t xo = (size_t)b * AD * AD;
    if (sel == 0)
        gemm_bf16_core<true>(g_Wqhi, g_Wqlo, g_Qhi + xo, g_Qlo + xo,
                             nullptr, g_QpThi + xo, g_QpTlo + xo, WQb, 1.0f);
    else
        gemm_bf16_core<true>(g_Wkhi, g_Wklo, g_Khi + xo, g_Klo + xo,
                             nullptr, g_KpThi + xo, g_KpTlo + xo, WKb, 1.0f);
}

// scores: am0[i][k] = (1/sqrt8) * sum_j QpT[i][j]*KpT[k][j]
__global__ void __maxnreg__(116) scores_kernel() {
    int b = blockIdx.z;
    size_t o = (size_t)b * AD * AD;
    gemm_bf16_core<false>(g_QpThi + o, g_QpTlo + o, g_KpThi + o, g_KpTlo + o,
                          g_am0 + o, nullptr, nullptr, nullptr,
                          0.3535533905932738f);
}

// ---------------- Vp = V @ WV^T + b  (16x512, tiny) ----------------
__global__ __launch_bounds__(256) void vproj(const float* __restrict__ V,
                                             const float* __restrict__ Ww,
                                             const float* __restrict__ Wb) {
    int b = blockIdx.x;
    int wid = threadIdx.x >> 5, lane = threadIdx.x & 31;
    const float* vr = V + b * AD;
#pragma unroll
    for (int ii = 0; ii < 4; ii++) {
        int i = blockIdx.y * 32 + wid * 4 + ii;
        const float* wr = Ww + (size_t)i * AD;
        float s = 0.f;
        for (int t = lane; t < AD; t += 32) s += vr[t] * wr[t];
#pragma unroll
        for (int o = 16; o; o >>= 1) s += __shfl_xor_sync(~0u, s, o);
        if (lane == 0) g_Vp[b * AD + i] = s + Wb[i];
    }
}

// ---------------- attn (mutate): block per (b,i); 8 warps = 8 heads ---------
__global__ __launch_bounds__(256) void attn_mut2() {
    int bid = blockIdx.x;             // b*512 + i
    int b = bid >> 9;
    int i = bid & (AD - 1);
    int tid = threadIdx.x;
    int h = tid >> 5, lane = tid & 31;
    __shared__ float am_s[AD];
    __shared__ float v_s[AD];
    const float* am = g_am0 + (size_t)b * AD * AD + (size_t)i * AD;
    const float* Vb = g_Vp + b * AD;
    for (int m = tid; m < AD; m += 256) { am_s[m] = am[m]; v_s[m] = Vb[m]; }
    __syncthreads();
    const unsigned* bp = g_bits + ((size_t)((b * HH + h) * AD + i) << 9);
    float s = 0.f, d = 0.f;
#pragma unroll
    for (int q = 0; q < 16; q++) {
        int k = lane + q * 32;
        float u = bits_to_unit(bp[k]);
        float m = fmaxf(0.7f, fmaf(u, 0.6f, 0.7f));
        float e = __expf(am_s[k] * m);
        s += e;
        d += e * v_s[k];
    }
#pragma unroll
    for (int o = 16; o; o >>= 1) {
        s += __shfl_xor_sync(~0u, s, o);
        d += __shfl_xor_sync(~0u, d, o);
    }
    if (lane == 0) g_att[(b * HH + h) * AD + i] = d / s;
}

struct CrossP { unsigned short r1[BB * HH]; unsigned short r2[BB * HH]; };

__global__ __launch_bounds__(256) void attn_cross(CrossP P) {
    int row = blockIdx.x * 8 + (threadIdx.x >> 5);
    int lane = threadIdx.x & 31;
    int i = row & (AD - 1);
    int bh = row >> 9;
    int b = row >> 12;
    int r1 = P.r1[bh], r2 = P.r2[bh];
    int tsrc = i;
    if (i == r1) tsrc = r2;
    else if (i == r2) tsrc = r1;
    const float* amb = g_am0 + (size_t)b * AD * AD;
    const float* ami = amb + (size_t)i * AD;
    const float* amt = amb + (size_t)tsrc * AD;
    const float* Vb = g_Vp + b * AD;
    float s = 0.f, d = 0.f;
#pragma unroll
    for (int q = 0; q < 16; q++) {
        int k = lane + q * 32;
        float v = (k >= CROSS_C) ? amt[k] : ami[k];
        float e = __expf(v);
        s += e;
        d += e * Vb[k];
    }
#pragma unroll
    for (int o = 16; o; o >>= 1) {
        s += __shfl_xor_sync(~0u, s, o);
        d += __shfl_xor_sync(~0u, d, o);
    }
    if (lane == 0) g_att[row] = d / s;
}

// ---------------- out = att(16,4096) @ WO_w(512,4096)^T + WO_b ----------------
__global__ __launch_bounds__(256) void outproj(const float* __restrict__ Ww,
                                               const float* __restrict__ Wb,
                                               float* __restrict__ out) {
    __shared__ float arow[HH * AD];
    int b = blockIdx.x;
    for (int m = threadIdx.x; m < HH * AD; m += 256)
        arow[m] = g_att[b * HH * AD + m];
    __syncthreads();
    int wid = threadIdx.x >> 5, lane = threadIdx.x & 31;
    const float4* ar = (const float4*)arow;
#pragma unroll
    for (int l = 0; l < 8; l++) {
        int n = blockIdx.y * 64 + wid * 8 + l;
        const float4* wr = (const float4*)(Ww + (size_t)n * (HH * AD));
        float s = 0.f;
        for (int m = lane; m < (HH * AD) / 4; m += 32) {
            float4 w = wr[m], a = ar[m];
            s += w.x * a.x + w.y * a.y + w.z * a.z + w.w * a.w;
        }
#pragma unroll
        for (int o = 16; o; o >>= 1) s += __shfl_xor_sync(~0u, s, o);
        if (lane == 0) out[b * AD + n] = s + Wb[n];
    }
}

// ---------------- host-side threefry (constant key 42; deterministic) -------
static inline unsigned h_rotl(unsigned x, int r) { return (x << r) | (x >> (32 - r)); }
static void h_tf2x32(unsigned k0, unsigned k1, unsigned x0, unsigned x1,
                     unsigned &o0, unsigned &o1) {
    unsigned k2 = k0 ^ k1 ^ 0x1BD11BDAu;
    x0 += k0; x1 += k1;
#define HTFR(r) { x0 += x1; x1 = h_rotl(x1, r); x1 ^= x0; }
    HTFR(13) HTFR(15) HTFR(26) HTFR(6)   x0 += k1; x1 += k2 + 1u;
    HTFR(17) HTFR(29) HTFR(16) HTFR(24)  x0 += k2; x1 += k0 + 2u;
    HTFR(13) HTFR(15) HTFR(26) HTFR(6)   x0 += k0; x1 += k1 + 3u;
    HTFR(17) HTFR(29) HTFR(16) HTFR(24)  x0 += k1; x1 += k2 + 4u;
    HTFR(13) HTFR(15) HTFR(26) HTFR(6)   x0 += k2; x1 += k0 + 5u;
#undef HTFR
    o0 = x0; o1 = x1;
}
static inline float h_bits_to_unit(unsigned bits) {
    union { unsigned u; float f; } c;
    c.u = (bits >> 9) | 0x3f800000u;
    return c.f - 1.0f;
}

// ---------------- launch ----------------
extern "C" void kernel_launch(void* const* d_in, const int* in_sizes, int n_in,
                              void* d_out, int out_size) {
    const float* Q   = (const float*)d_in[0];
    const float* K   = (const float*)d_in[1];
    const float* V   = (const float*)d_in[2];
    const float* WQw = (const float*)d_in[3];
    const float* WQb = (const float*)d_in[4];
    const float* WKw = (const float*)d_in[5];
    const float* WKb = (const float*)d_in[6];
    const float* WVw = (const float*)d_in[7];
    const float* WVb = (const float*)d_in[8];
    const float* WOw = (const float*)d_in[9];
    const float* WOb = (const float*)d_in[10];
    float* out = (float*)d_out;

    static int inited = 0, sok = 0;
    static cudaStream_t s2;
    static cudaEvent_t evF, evJ;
    if (!inited) {
        inited = 1;
        cudaFuncSetAttribute(proj_kernel,
            cudaFuncAttributeMaxDynamicSharedMemorySize, GEMM_SMEM_BYTES);
        cudaFuncSetAttribute(scores_kernel,
            cudaFuncAttributeMaxDynamicSharedMemorySize, GEMM_SMEM_BYTES);
        sok = (cudaStreamCreateWithFlags(&s2, cudaStreamNonBlocking) == cudaSuccess) &&
              (cudaEventCreateWithFlags(&evF, cudaEventDisableTiming) == cudaSuccess) &&
              (cudaEventCreateWithFlags(&evJ, cudaEventDisableTiming) == cudaSuccess);
    }

    // host RNG setup (pure constants from key 42)
    unsigned kp0, kp1, km0, km1, ka0, ka1, kb0, kb1;
    h_tf2x32(0u, 42u, 0u, 0u, kp0, kp1);
    h_tf2x32(0u, 42u, 0u, 1u, km0, km1);
    h_tf2x32(0u, 42u, 0u, 2u, ka0, ka1);
    h_tf2x32(0u, 42u, 0u, 3u, kb0, kb1);
    unsigned b0, b1;
    h_tf2x32(kp0, kp1, 0u, 0u, b0, b1);
    int mutate = (h_bits_to_unit(b0 ^ b1) <= 0.6f) ? 1 : 0;

    if (mutate && sok) {
        // fork: vproj + threefry run concurrently with prepass/GEMM phase.
        // mut_pre blocks are reg-capped to co-reside with the GEMM CTAs.
        cudaEventRecord(evF, 0);
        cudaStreamWaitEvent(s2, evF, 0);
        vproj<<<dim3(BB, 16), 256, 0, s2>>>(V, WVw, WVb);
        mut_pre<<<4096, 128, 0, s2>>>(km0, km1);
        cudaEventRecord(evJ, s2);
    } else if (mutate) {
        vproj<<<dim3(BB, 16), 256>>>(V, WVw, WVb);
        mut_pre<<<4096, 128>>>(km0, km1);
    } else {
        vproj<<<dim3(BB, 16), 256>>>(V, WVw, WVb);
    }

    split_pre<<<2048, 256>>>(Q, K, WQw, WKw);
    proj_kernel<<<dim3(4, 4, 32), 256, GEMM_SMEM_BYTES>>>(WQb, WKb);
    scores_kernel<<<dim3(4, 4, 16), 256, GEMM_SMEM_BYTES>>>();

    if (mutate) {
        if (sok) cudaStreamWaitEvent(0, evJ, 0);
        attn_mut2<<<BB * AD, 256>>>();
    } else {
        CrossP P;
        unsigned s0, s1, l0, l1;
        h_tf2x32(ka0, ka1, 0u, 1u, s0, s1);
        for (int t = 0; t < BB * HH; t++) {
            h_tf2x32(s0, s1, 0u, (unsigned)t, l0, l1);
            P.r1[t] = (unsigned short)((l0 ^ l1) & (AD - 1u));
        }
        h_tf2x32(kb0, kb1, 0u, 1u, s0, s1);
        for (int t = 0; t < BB * HH; t++) {
            h_tf2x32(s0, s1, 0u, (unsigned)t, l0, l1);
            P.r2[t] = (unsigned short)((l0 ^ l1) & (AD - 1u));
        }
        attn_cross<<<BB * HH * AD / 8, 256>>>(P);
    }
    outproj<<<dim3(BB, 8), 256>>>(WOw, WOb, out);
}

// round 16
// speedup vs baseline: 1.0607x; 1.0607x over previous
#include <cuda_runtime.h>
#include <cuda_bf16.h>
#include <cstdint>

#define AD 512
#define BB 16
#define HH 8
#define CROSS_C 359   // A - int(A*0.3) = 512 - 153

// ---------------- scratch (static device globals; no allocs) ----------------
__device__ __nv_bfloat16 g_Qhi[BB * AD * AD], g_Qlo[BB * AD * AD];
__device__ __nv_bfloat16 g_Khi[BB * AD * AD], g_Klo[BB * AD * AD];
__device__ __nv_bfloat16 g_Wqhi[AD * AD], g_Wqlo[AD * AD];
__device__ __nv_bfloat16 g_Wkhi[AD * AD], g_Wklo[AD * AD];
__device__ __nv_bfloat16 g_QpThi[BB * AD * AD], g_QpTlo[BB * AD * AD];
__device__ __nv_bfloat16 g_KpThi[BB * AD * AD], g_KpTlo[BB * AD * AD];
__device__ float g_am0[BB * AD * AD];
__device__ float g_Vp[BB * AD];
__device__ float g_att[BB * HH * AD];

// ---------------- threefry2x32 (20 rounds, JAX-compatible) ----------------
__device__ __forceinline__ void tf2x32(unsigned k0, unsigned k1,
                                       unsigned x0, unsigned x1,
                                       unsigned &o0, unsigned &o1) {
    unsigned k2 = k0 ^ k1 ^ 0x1BD11BDAu;
    x0 += k0; x1 += k1;
#define TFR(r) { x0 += x1; x1 = __funnelshift_l(x1, x1, r); x1 ^= x0; }
    TFR(13) TFR(15) TFR(26) TFR(6)   x0 += k1; x1 += k2 + 1u;
    TFR(17) TFR(29) TFR(16) TFR(24)  x0 += k2; x1 += k0 + 2u;
    TFR(13) TFR(15) TFR(26) TFR(6)   x0 += k0; x1 += k1 + 3u;
    TFR(17) TFR(29) TFR(16) TFR(24)  x0 += k1; x1 += k2 + 4u;
    TFR(13) TFR(15) TFR(26) TFR(6)   x0 += k2; x1 += k0 + 5u;
#undef TFR
    o0 = x0; o1 = x1;
}

__device__ __forceinline__ float bits_to_unit(unsigned bits) {
    return __uint_as_float((bits >> 9) | 0x3f800000u) - 1.0f;
}

// ---------------- bf16 split helpers ----------------
__device__ __forceinline__ void split_bf16(float x, __nv_bfloat16 &hi, __nv_bfloat16 &lo) {
    hi = __float2bfloat16_rn(x);
    lo = __float2bfloat16_rn(x - __bfloat162float(hi));
}

__device__ __forceinline__ void mma_bf16(float* c, const unsigned* a, const unsigned* b) {
    asm volatile(
        "mma.sync.aligned.m16n8k16.row.col.f32.bf16.bf16.f32 "
        "{%0,%1,%2,%3}, {%4,%5,%6,%7}, {%8,%9}, {%0,%1,%2,%3};"
        : "+f"(c[0]), "+f"(c[1]), "+f"(c[2]), "+f"(c[3])
        : "r"(a[0]), "r"(a[1]), "r"(a[2]), "r"(a[3]), "r"(b[0]), "r"(b[1]));
}

__device__ __forceinline__ void ldsm_x4(unsigned* r, unsigned addr) {
    asm volatile("ldmatrix.sync.aligned.m8n8.x4.shared.b16 {%0,%1,%2,%3}, [%4];"
                 : "=r"(r[0]), "=r"(r[1]), "=r"(r[2]), "=r"(r[3]) : "r"(addr));
}
__device__ __forceinline__ void ldsm_x2(unsigned* r, unsigned addr) {
    asm volatile("ldmatrix.sync.aligned.m8n8.x2.shared.b16 {%0,%1}, [%2];"
                 : "=r"(r[0]), "=r"(r[1]) : "r"(addr));
}

#define CP16(dst_s, src_g) \
    asm volatile("cp.async.cg.shared.global [%0], [%1], 16;\n" :: "r"(dst_s), "l"(src_g))
#define CP_COMMIT asm volatile("cp.async.commit_group;\n" ::)
#define CP_WAIT(n) asm volatile("cp.async.wait_group %0;\n" :: "n"(n))

__device__ __forceinline__ unsigned saddr(const void* p) {
    return (unsigned)__cvta_generic_to_shared(p);
}

// ---------------- prepass: split fp32 inputs into bf16 hi/lo ----------------
__global__ __launch_bounds__(256) void split_pre(const float* __restrict__ Q,
                                                 const float* __restrict__ K,
                                                 const float* __restrict__ WQw,
                                                 const float* __restrict__ WKw) {
    const int N1 = BB * AD * AD;
    const int N2 = AD * AD;
    const int total4 = (2 * N1 + 2 * N2) / 4;
    for (int v = blockIdx.x * blockDim.x + threadIdx.x; v < total4;
         v += gridDim.x * blockDim.x) {
        int i = v * 4;
        const float* src; __nv_bfloat16 *dh, *dl; int off;
        if (i < N1)              { src = Q;   dh = g_Qhi;  dl = g_Qlo;  off = i; }
        else if (i < 2 * N1)     { src = K;   dh = g_Khi;  dl = g_Klo;  off = i - N1; }
        else if (i < 2 * N1 + N2){ src = WQw; dh = g_Wqhi; dl = g_Wqlo; off = i - 2 * N1; }
        else                     { src = WKw; dh = g_Wkhi; dl = g_Wklo; off = i - 2 * N1 - N2; }
        float4 x = *(const float4*)(src + off);
        __nv_bfloat16 h[4], l[4];
        split_bf16(x.x, h[0], l[0]);
        split_bf16(x.y, h[1], l[1]);
        split_bf16(x.z, h[2], l[2]);
        split_bf16(x.w, h[3], l[3]);
        *(uint2*)(dh + off) = *(uint2*)h;
        *(uint2*)(dl + off) = *(uint2*)l;
    }
}

// ---------------- 3xBF16 TN GEMM with ldmatrix ------------------------------
// CTA 128x128, 8 warps (2x4), warp tile 64x32, BK=16, m16n8k16 bf16 mma.
// Smem rows padded to 48B so ldmatrix row-addresses are bank-conflict-free.
// 4 stages (96 KB) -> 2 CTAs/SM = 16 warps/SM.
#define NSTAGE 4
#define ROWB 48
#define ARR_B (128 * ROWB)               // 6144 B per array
#define STAGE_B (4 * ARR_B)              // 24576 B per stage
#define GEMM_SMEM_BYTES (NSTAGE * STAGE_B)   // 96 KB

template<bool SPLIT_OUT>
__device__ __forceinline__ void gemm_bf16_core(
    const __nv_bfloat16* __restrict__ Ahi, const __nv_bfloat16* __restrict__ Alo,
    const __nv_bfloat16* __restrict__ Bhi, const __nv_bfloat16* __restrict__ Blo,
    float* __restrict__ Cf, __nv_bfloat16* __restrict__ Chi,
    __nv_bfloat16* __restrict__ Clo,
    const float* __restrict__ bias, float scale) {
    extern __shared__ char smb[];
    const unsigned smem_u = saddr(smb);
    int tid = threadIdx.x;
    int lane = tid & 31, wid = tid >> 5;
    int wm = wid & 1, wn = wid >> 1;       // 2 x 4 warp grid
    int m0 = blockIdx.y * 128, n0 = blockIdx.x * 128;
    int qr = lane >> 2, qc = lane & 3;

    float acc[4][4][4];
#pragma unroll
    for (int mi = 0; mi < 4; mi++)
#pragma unroll
        for (int ni = 0; ni < 4; ni++)
#pragma unroll
            for (int e = 0; e < 4; e++) acc[mi][ni][e] = 0.f;

    int lr = tid >> 1;            // row 0..127
    int lc = (tid & 1) * 8;       // element 0 or 8

#define ISSUE(ch, st)                                                          \
    {                                                                          \
        int k0_ = (ch) * 16 + lc;                                              \
        unsigned d_ = smem_u + (st) * STAGE_B + lr * ROWB + lc * 2;            \
        CP16(d_,              Ahi + (size_t)(m0 + lr) * AD + k0_);             \
        CP16(d_ + ARR_B,      Alo + (size_t)(m0 + lr) * AD + k0_);             \
        CP16(d_ + 2 * ARR_B,  Bhi + (size_t)(n0 + lr) * AD + k0_);             \
        CP16(d_ + 3 * ARR_B,  Blo + (size_t)(n0 + lr) * AD + k0_);             \
        CP_COMMIT;                                                             \
    }

    ISSUE(0, 0)
    ISSUE(1, 1)
    ISSUE(2, 2)

    // per-lane ldmatrix address offsets (within an array)
    unsigned a_off = (unsigned)((wm * 64 + (lane & 15)) * ROWB + ((lane >> 4) << 4));
    unsigned b_off = (unsigned)((wn * 32 + (lane & 7)) * ROWB + (((lane >> 3) & 1) << 4));

    const int NIT = AD / 16;   // 32
    for (int it = 0; it < NIT; ++it) {
        int s = it & (NSTAGE - 1);
        int rem = NIT - 1 - it;
        if (rem >= 2) CP_WAIT(2); else if (rem == 1) CP_WAIT(1); else CP_WAIT(0);
        __syncthreads();
        if (it + 3 < NIT) ISSUE(it + 3, (it + 3) & (NSTAGE - 1))

        unsigned base = smem_u + s * STAGE_B;
        unsigned ah[4][4], al[4][4];
#pragma unroll
        for (int mi = 0; mi < 4; mi++) {
            unsigned addr = base + a_off + mi * (16 * ROWB);
            ldsm_x4(ah[mi], addr);
            ldsm_x4(al[mi], addr + ARR_B);
        }
#pragma unroll
        for (int ni = 0; ni < 4; ni++) {
            unsigned addrB = base + 2 * ARR_B + b_off + ni * (8 * ROWB);
            unsigned bh[2], bl[2];
            ldsm_x2(bh, addrB);
            ldsm_x2(bl, addrB + ARR_B);
#pragma unroll
            for (int mi = 0; mi < 4; mi++) {
                mma_bf16(acc[mi][ni], ah[mi], bh);
                mma_bf16(acc[mi][ni], ah[mi], bl);
                mma_bf16(acc[mi][ni], al[mi], bh);
            }
        }
    }
#undef ISSUE

    // epilogue
#pragma unroll
    for (int mi = 0; mi < 4; mi++) {
        int r0 = m0 + wm * 64 + mi * 16 + qr;
        float b0 = 0.f, b1 = 0.f;
        if (bias) { b0 = __ldg(bias + r0); b1 = __ldg(bias + r0 + 8); }
#pragma unroll
        for (int ni = 0; ni < 4; ni++) {
            int c0 = n0 + wn * 32 + ni * 8 + qc * 2;
            float v00 = acc[mi][ni][0] * scale + b0;
            float v01 = acc[mi][ni][1] * scale + b0;
            float v10 = acc[mi][ni][2] * scale + b1;
            float v11 = acc[mi][ni][3] * scale + b1;
            if (SPLIT_OUT) {
                __nv_bfloat16 h[2], l[2];
                split_bf16(v00, h[0], l[0]);
                split_bf16(v01, h[1], l[1]);
                *(unsigned*)&Chi[(size_t)r0 * AD + c0] = *(unsigned*)h;
                *(unsigned*)&Clo[(size_t)r0 * AD + c0] = *(unsigned*)l;
                split_bf16(v10, h[0], l[0]);
                split_bf16(v11, h[1], l[1]);
                *(unsigned*)&Chi[(size_t)(r0 + 8) * AD + c0] = *(unsigned*)h;
                *(unsigned*)&Clo[(size_t)(r0 + 8) * AD + c0] = *(unsigned*)l;
            } else {
                float2 v0 = {v00, v01}, v1 = {v10, v11};
                *(float2*)&Cf[(size_t)r0 * AD + c0] = v0;
                *(float2*)&Cf[(size_t)(r0 + 8) * AD + c0] = v1;
            }
        }
    }
}

// merged Q/K projection: QpT[i][j] = sum_t W[i,t]*X[j,t] + bias[i] (split out)
__global__ __launch_bounds__(256, 2) void proj_kernel(
    const float* __restrict__ WQb, const float* __restrict__ WKb) {
    int z = blockIdx.z;
    int b = z & (BB - 1);
    int sel = z >> 4;
    size_t xo = (size_t)b * AD * AD;
    if (sel == 0)
        gemm_bf16_core<true>(g_Wqhi, g_Wqlo, g_Qhi + xo, g_Qlo + xo,
                             nullptr, g_QpThi + xo, g_QpTlo + xo, WQb, 1.0f);
    else
        gemm_bf16_core<true>(g_Wkhi, g_Wklo, g_Khi + xo, g_Klo + xo,
                             nullptr, g_KpThi + xo, g_KpTlo + xo, WKb, 1.0f);
}

// scores: am0[i][k] = (1/sqrt8) * sum_j QpT[i][j]*KpT[k][j]
__global__ __launch_bounds__(256, 2) void scores_kernel() {
    int b = blockIdx.z;
    size_t o = (size_t)b * AD * AD;
    gemm_bf16_core<false>(g_QpThi + o, g_QpTlo + o, g_KpThi + o, g_KpTlo + o,
                          g_am0 + o, nullptr, nullptr, nullptr,
                          0.3535533905932738f);
}

// ---------------- Vp = V @ WV^T + b  (16x512, tiny) ----------------
__global__ __launch_bounds__(256) void vproj(const float* __restrict__ V,
                                             const float* __restrict__ Ww,
                                             const float* __restrict__ Wb) {
    int b = blockIdx.x;
    int wid = threadIdx.x >> 5, lane = threadIdx.x & 31;
    const float* vr = V + b * AD;
#pragma unroll
    for (int ii = 0; ii < 4; ii++) {
        int i = blockIdx.y * 32 + wid * 4 + ii;
        const float* wr = Ww + (size_t)i * AD;
        float s = 0.f;
        for (int t = lane; t < AD; t += 32) s += vr[t] * wr[t];
#pragma unroll
        for (int o = 16; o; o >>= 1) s += __shfl_xor_sync(~0u, s, o);
        if (lane == 0) g_Vp[b * AD + i] = s + Wb[i];
    }
}

// ---------------- attn (mutate): warp-per-row, threefry fused inline --------
// measured R5: 107.6us, occ 92.6%, alu 83.6% -> ALU roofline, no g_bits traffic
struct MutP { unsigned km0, km1; };

__global__ __launch_bounds__(256) void attn_mut(MutP P) {
    int row = blockIdx.x * 8 + (threadIdx.x >> 5);   // (b*8+h)*512 + i
    int lane = threadIdx.x & 31;
    int i = row & (AD - 1);
    int b = row >> 12;
    const float* am = g_am0 + (size_t)b * AD * AD + (size_t)i * AD;
    const float* Vb = g_Vp + b * AD;
    unsigned base = ((unsigned)row) << 9;
    float s = 0.f, d = 0.f;
#pragma unroll 4
    for (int q = 0; q < 16; q++) {
        int k = lane + q * 32;
        unsigned o0, o1;
        tf2x32(P.km0, P.km1, 0u, base + (unsigned)k, o0, o1);
        float u = bits_to_unit(o0 ^ o1);
        float m = fmaxf(0.7f, fmaf(u, 0.6f, 0.7f));
        float e = __expf(am[k] * m);
        s += e;
        d += e * Vb[k];
    }
#pragma unroll
    for (int o = 16; o; o >>= 1) {
        s += __shfl_xor_sync(~0u, s, o);
        d += __shfl_xor_sync(~0u, d, o);
    }
    if (lane == 0) g_att[row] = d / s;
}

struct CrossP { unsigned short r1[BB * HH]; unsigned short r2[BB * HH]; };

__global__ __launch_bounds__(256) void attn_cross(CrossP P) {
    int row = blockIdx.x * 8 + (threadIdx.x >> 5);
    int lane = threadIdx.x & 31;
    int i = row & (AD - 1);
    int bh = row >> 9;
    int b = row >> 12;
    int r1 = P.r1[bh], r2 = P.r2[bh];
    int tsrc = i;
    if (i == r1) tsrc = r2;
    else if (i == r2) tsrc = r1;
    const float* amb = g_am0 + (size_t)b * AD * AD;
    const float* ami = amb + (size_t)i * AD;
    const float* amt = amb + (size_t)tsrc * AD;
    const float* Vb = g_Vp + b * AD;
    float s = 0.f, d = 0.f;
#pragma unroll
    for (int q = 0; q < 16; q++) {
        int k = lane + q * 32;
        float v = (k >= CROSS_C) ? amt[k] : ami[k];
        float e = __expf(v);
        s += e;
        d += e * Vb[k];
    }
#pragma unroll
    for (int o = 16; o; o >>= 1) {
        s += __shfl_xor_sync(~0u, s, o);
        d += __shfl_xor_sync(~0u, d, o);
    }
    if (lane == 0) g_att[row] = d / s;
}

// ---------------- out = att(16,4096) @ WO_w(512,4096)^T + WO_b ----------------
__global__ __launch_bounds__(256) void outproj(const float* __restrict__ Ww,
                                               const float* __restrict__ Wb,
                                               float* __restrict__ out) {
    __shared__ float arow[HH * AD];
    int b = blockIdx.x;
    for (int m = threadIdx.x; m < HH * AD; m += 256)
        arow[m] = g_att[b * HH * AD + m];
    __syncthreads();
    int wid = threadIdx.x >> 5, lane = threadIdx.x & 31;
    const float4* ar = (const float4*)arow;
#pragma unroll
    for (int l = 0; l < 8; l++) {
        int n = blockIdx.y * 64 + wid * 8 + l;
        const float4* wr = (const float4*)(Ww + (size_t)n * (HH * AD));
        float s = 0.f;
        for (int m = lane; m < (HH * AD) / 4; m += 32) {
            float4 w = wr[m], a = ar[m];
            s += w.x * a.x + w.y * a.y + w.z * a.z + w.w * a.w;
        }
#pragma unroll
        for (int o = 16; o; o >>= 1) s += __shfl_xor_sync(~0u, s, o);
        if (lane == 0) out[b * AD + n] = s + Wb[n];
    }
}

// ---------------- host-side threefry (constant key 42; deterministic) -------
static inline unsigned h_rotl(unsigned x, int r) { return (x << r) | (x >> (32 - r)); }
static void h_tf2x32(unsigned k0, unsigned k1, unsigned x0, unsigned x1,
                     unsigned &o0, unsigned &o1) {
    unsigned k2 = k0 ^ k1 ^ 0x1BD11BDAu;
    x0 += k0; x1 += k1;
#define HTFR(r) { x0 += x1; x1 = h_rotl(x1, r); x1 ^= x0; }
    HTFR(13) HTFR(15) HTFR(26) HTFR(6)   x0 += k1; x1 += k2 + 1u;
    HTFR(17) HTFR(29) HTFR(16) HTFR(24)  x0 += k2; x1 += k0 + 2u;
    HTFR(13) HTFR(15) HTFR(26) HTFR(6)   x0 += k0; x1 += k1 + 3u;
    HTFR(17) HTFR(29) HTFR(16) HTFR(24)  x0 += k1; x1 += k2 + 4u;
    HTFR(13) HTFR(15) HTFR(26) HTFR(6)   x0 += k2; x1 += k0 + 5u;
#undef HTFR
    o0 = x0; o1 = x1;
}
static inline float h_bits_to_unit(unsigned bits) {
    union { unsigned u; float f; } c;
    c.u = (bits >> 9) | 0x3f800000u;
    return c.f - 1.0f;
}

// ---------------- launch ----------------
extern "C" void kernel_launch(void* const* d_in, const int* in_sizes, int n_in,
                              void* d_out, int out_size) {
    const float* Q   = (const float*)d_in[0];
    const float* K   = (const float*)d_in[1];
    const float* V   = (const float*)d_in[2];
    const float* WQw = (const float*)d_in[3];
    const float* WQb = (const float*)d_in[4];
    const float* WKw = (const float*)d_in[5];
    const float* WKb = (const float*)d_in[6];
    const float* WVw = (const float*)d_in[7];
    const float* WVb = (const float*)d_in[8];
    const float* WOw = (const float*)d_in[9];
    const float* WOb = (const float*)d_in[10];
    float* out = (float*)d_out;

    static int inited = 0, sok = 0;
    static cudaStream_t s2;
    static cudaEvent_t evF, evJ;
    if (!inited) {
        inited = 1;
        cudaFuncSetAttribute(proj_kernel,
            cudaFuncAttributeMaxDynamicSharedMemorySize, GEMM_SMEM_BYTES);
        cudaFuncSetAttribute(scores_kernel,
            cudaFuncAttributeMaxDynamicSharedMemorySize, GEMM_SMEM_BYTES);
        sok = (cudaStreamCreateWithFlags(&s2, cudaStreamNonBlocking) == cudaSuccess) &&
              (cudaEventCreateWithFlags(&evF, cudaEventDisableTiming) == cudaSuccess) &&
              (cudaEventCreateWithFlags(&evJ, cudaEventDisableTiming) == cudaSuccess);
    }

    // host RNG setup (pure constants from key 42)
    unsigned kp0, kp1, km0, km1, ka0, ka1, kb0, kb1;
    h_tf2x32(0u, 42u, 0u, 0u, kp0, kp1);
    h_tf2x32(0u, 42u, 0u, 1u, km0, km1);
    h_tf2x32(0u, 42u, 0u, 2u, ka0, ka1);
    h_tf2x32(0u, 42u, 0u, 3u, kb0, kb1);
    unsigned b0, b1;
    h_tf2x32(kp0, kp1, 0u, 0u, b0, b1);
    int mutate = (h_bits_to_unit(b0 ^ b1) <= 0.6f) ? 1 : 0;

    if (sok) {
        // fork: vproj runs concurrently with prepass/GEMM phase
        cudaEventRecord(evF, 0);
        cudaStreamWaitEvent(s2, evF, 0);
        vproj<<<dim3(BB, 16), 256, 0, s2>>>(V, WVw, WVb);
        cudaEventRecord(evJ, s2);
    } else {
        vproj<<<dim3(BB, 16), 256>>>(V, WVw, WVb);
    }

    split_pre<<<2048, 256>>>(Q, K, WQw, WKw);
    proj_kernel<<<dim3(4, 4, 32), 256, GEMM_SMEM_BYTES>>>(WQb, WKb);
    scores_kernel<<<dim3(4, 4, 16), 256, GEMM_SMEM_BYTES>>>();

    if (sok) cudaStreamWaitEvent(0, evJ, 0);

    if (mutate) {
        MutP P; P.km0 = km0; P.km1 = km1;
        attn_mut<<<BB * HH * AD / 8, 256>>>(P);
    } else {
        CrossP P;
        unsigned s0, s1, l0, l1;
        h_tf2x32(ka0, ka1, 0u, 1u, s0, s1);
        for (int t = 0; t < BB * HH; t++) {
            h_tf2x32(s0, s1, 0u, (unsigned)t, l0, l1);
            P.r1[t] = (unsigned short)((l0 ^ l1) & (AD - 1u));
        }
        h_tf2x32(kb0, kb1, 0u, 1u, s0, s1);
        for (int t = 0; t < BB * HH; t++) {
            h_tf2x32(s0, s1, 0u, (unsigned)t, l0, l1);
            P.r2[t] = (unsigned short)((l0 ^ l1) & (AD - 1u));
        }
        attn_cross<<<BB * HH * AD / 8, 256>>>(P);
    }
    outproj<<<dim3(BB, 8), 256>>>(WOw, WOb, out);
}